// round 4
// baseline (speedup 1.0000x reference)
#include <cuda_runtime.h>

#define VDIM 128
#define NB   8
#define SLAB 16384
#define VOL  2097152

// Scratch spectrum: 8 * 128^3 complex = 134 MB (static device alloc allowed).
__device__ float2 g_Z[(size_t)NB * VOL];

__device__ __forceinline__ int brev7(int x) { return (int)(__brev((unsigned)x) >> 25); }
__device__ __forceinline__ int bneg7(int j) {
    int k = brev7(j); k = (VDIM - k) & 127; return brev7(k);
}

// passA/C tile swizzle (row stride 128; XOR spread).
__device__ __forceinline__ int sidxAC(int y, int x) {
    int c = x ^ ((x >> 4) & 7) ^ ((x & 1) << 3)
              ^ (y & 7) ^ ((y >> 4) & 7) ^ ((y & 1) << 3);
    return (y << 7) + c;
}
// passB tile swizzle for lane map t=(tid>>4)&7, l=(tid>>7)<<4|(tid&15):
// every phase's half-warp varies either z's low bits or l's low 4 bits.
__device__ __forceinline__ int sidxB(int l, int z) {
    int c = z ^ ((z >> 4) & 7) ^ (l & 15);
    return (l << 7) + c;
}

__device__ __forceinline__ float2 cmul(float2 a, float2 w) {
    return make_float2(a.x * w.x - a.y * w.y, a.x * w.y + a.y * w.x);
}
__device__ __forceinline__ float2 cmulc(float2 a, float2 w) {
    return make_float2(a.x * w.x + a.y * w.y, a.y * w.x - a.x * w.y);
}
__device__ __forceinline__ void bf_fwd(float2& ra, float2& rb, float2 w) {
    float2 a = ra, b = rb;
    ra = make_float2(a.x + b.x, a.y + b.y);
    rb = cmul(make_float2(a.x - b.x, a.y - b.y), w);
}
__device__ __forceinline__ void bf_inv(float2& ra, float2& rb, float2 w) {
    float2 a = ra, t = cmulc(rb, w);
    ra = make_float2(a.x + t.x, a.y + t.y);
    rb = make_float2(a.x - t.x, a.y - t.y);
}

// Pattern A: r[j] = x[t + 8j].  Forward DIF stages half = 64,32,16,8.
__device__ __forceinline__ void fftA_fwd(float2 r[16], int t, const float2* tw,
                                         const float2* tw4, const float2* tw8) {
    #pragma unroll
    for (int j = 0; j < 8; ++j) bf_fwd(r[j], r[j + 8], tw[t + 8 * j]);
    #pragma unroll
    for (int g = 0; g < 8; ++g) { int j = ((g & ~3) << 1) | (g & 3); bf_fwd(r[j], r[j + 4], tw[2 * (t + 8 * (j & 3))]); }
    #pragma unroll
    for (int g = 0; g < 8; ++g) { int j = ((g & ~1) << 1) | (g & 1); bf_fwd(r[j], r[j + 2], tw4[t + 8 * (j & 1)]); }
    #pragma unroll
    for (int g = 0; g < 8; ++g) { int j = 2 * g; bf_fwd(r[j], r[j + 1], tw8[t]); }
}
__device__ __forceinline__ void fftA_inv(float2 r[16], int t, const float2* tw,
                                         const float2* tw4, const float2* tw8) {
    #pragma unroll
    for (int g = 0; g < 8; ++g) { int j = 2 * g; bf_inv(r[j], r[j + 1], tw8[t]); }
    #pragma unroll
    for (int g = 0; g < 8; ++g) { int j = ((g & ~1) << 1) | (g & 1); bf_inv(r[j], r[j + 2], tw4[t + 8 * (j & 1)]); }
    #pragma unroll
    for (int g = 0; g < 8; ++g) { int j = ((g & ~3) << 1) | (g & 3); bf_inv(r[j], r[j + 4], tw[2 * (t + 8 * (j & 3))]); }
    #pragma unroll
    for (int j = 0; j < 8; ++j) bf_inv(r[j], r[j + 8], tw[t + 8 * j]);
}
// Pattern B: r[m] = x[16u + m].  Forward DIF stages half = 4,2,1.
__device__ __forceinline__ void fftB_fwd(float2 r[16], const float2* tw) {
    #pragma unroll
    for (int g = 0; g < 8; ++g) { int m = ((g & ~3) << 1) | (g & 3); bf_fwd(r[m], r[m + 4], tw[(m & 3) << 4]); }
    #pragma unroll
    for (int g = 0; g < 8; ++g) { int m = ((g & ~1) << 1) | (g & 1); bf_fwd(r[m], r[m + 2], tw[(m & 1) << 5]); }
    #pragma unroll
    for (int g = 0; g < 8; ++g) {
        int m = 2 * g; float2 a = r[m], b = r[m + 1];
        r[m] = make_float2(a.x + b.x, a.y + b.y);
        r[m + 1] = make_float2(a.x - b.x, a.y - b.y);
    }
}
__device__ __forceinline__ void fftB_inv(float2 r[16], const float2* tw) {
    #pragma unroll
    for (int g = 0; g < 8; ++g) {
        int m = 2 * g; float2 a = r[m], b = r[m + 1];
        r[m] = make_float2(a.x + b.x, a.y + b.y);
        r[m + 1] = make_float2(a.x - b.x, a.y - b.y);
    }
    #pragma unroll
    for (int g = 0; g < 8; ++g) { int m = ((g & ~1) << 1) | (g & 1); bf_inv(r[m], r[m + 2], tw[(m & 1) << 5]); }
    #pragma unroll
    for (int g = 0; g < 8; ++g) { int m = ((g & ~3) << 1) | (g & 3); bf_inv(r[m], r[m + 4], tw[(m & 3) << 4]); }
}

__device__ __forceinline__ void init_tw(float2* tw, float2* tw4, float2* tw8) {
    for (int i = threadIdx.x; i < 64; i += blockDim.x) {
        float sn, cs; sincospif(i * (1.0f / 64.0f), &sn, &cs);
        float2 w = make_float2(cs, -sn);
        tw[i] = w;
        if (!(i & 3)) tw4[i >> 2] = w;
        if (!(i & 7)) tw8[i >> 3] = w;
    }
}

// Pass A: pack v1 + i*v2, forward FFT along x then y per (b,z) slab.
__global__ __launch_bounds__(512) void passA(const float* __restrict__ v1,
                                             const float* __restrict__ v2) {
    extern __shared__ float2 sm[];
    float2* tile = sm;
    float2* tw = sm + 128 * 128; float2* tw4 = tw + 64; float2* tw8 = tw4 + 16;
    init_tw(tw, tw4, tw8);
    const int tid = threadIdx.x, w = tid >> 5, lane = tid & 31;
    const int t = lane & 7, q = (lane >> 3) & 1, h = lane >> 4;
    const int B0 = 2 * (w & 7) + 32 * (w >> 3);
    const size_t base = (size_t)blockIdx.x * SLAB;
    float2 r[16];
    __syncthreads();
    // copy-in: warp loads its 8 A_x rows coalesced (LDG.128 + conflict-free STS)
    #pragma unroll
    for (int c8 = 0; c8 < 8; ++c8) {
        const int y = B0 + 16 * (c8 & 1) + ((c8 >> 1) & 1) + 64 * (c8 >> 2);
        const float4 a = *(const float4*)(v1 + base + y * VDIM + 4 * lane);
        const float4 b = *(const float4*)(v2 + base + y * VDIM + 4 * lane);
        tile[sidxAC(y, 4 * lane + 0)] = make_float2(a.x, b.x);
        tile[sidxAC(y, 4 * lane + 1)] = make_float2(a.y, b.y);
        tile[sidxAC(y, 4 * lane + 2)] = make_float2(a.z, b.z);
        tile[sidxAC(y, 4 * lane + 3)] = make_float2(a.w, b.w);
    }
    __syncwarp();
    #pragma unroll 1
    for (int rep = 0; rep < 2; ++rep) {            // x-dim, pattern A
        const int y = B0 + 16 * q + h + 64 * rep;
        #pragma unroll
        for (int j = 0; j < 16; ++j) r[j] = tile[sidxAC(y, t + 8 * j)];
        fftA_fwd(r, t, tw, tw4, tw8);
        #pragma unroll
        for (int j = 0; j < 16; ++j) tile[sidxAC(y, t + 8 * j)] = r[j];
    }
    __syncwarp();
    #pragma unroll 1
    for (int rep = 0; rep < 2; ++rep) {            // x-dim, pattern B
        const int y = B0 + q + 16 * h + 64 * rep;
        #pragma unroll
        for (int m = 0; m < 16; ++m) r[m] = tile[sidxAC(y, 16 * t + m)];
        fftB_fwd(r, tw);
        #pragma unroll
        for (int m = 0; m < 16; ++m) tile[sidxAC(y, 16 * t + m)] = r[m];
    }
    __syncthreads();
    #pragma unroll 1
    for (int rep = 0; rep < 2; ++rep) {            // y-dim, pattern A
        const int x = B0 + 16 * q + h + 64 * rep;
        #pragma unroll
        for (int j = 0; j < 16; ++j) r[j] = tile[sidxAC(t + 8 * j, x)];
        fftA_fwd(r, t, tw, tw4, tw8);
        #pragma unroll
        for (int j = 0; j < 16; ++j) tile[sidxAC(t + 8 * j, x)] = r[j];
    }
    __syncwarp();
    #pragma unroll 1
    for (int rep = 0; rep < 2; ++rep) {            // y-dim, pattern B (write back)
        const int x = B0 + q + 16 * h + 64 * rep;
        #pragma unroll
        for (int m = 0; m < 16; ++m) r[m] = tile[sidxAC(16 * t + m, x)];
        fftB_fwd(r, tw);
        #pragma unroll
        for (int m = 0; m < 16; ++m) tile[sidxAC(16 * t + m, x)] = r[m];
    }
    __syncthreads();
    // copy-out: warp stores its 8 rows coalesced (LDS + STG.128)
    #pragma unroll
    for (int c8 = 0; c8 < 8; ++c8) {
        const int y = B0 + 16 * (c8 & 1) + ((c8 >> 1) & 1) + 64 * (c8 >> 2);
        float2 c0 = tile[sidxAC(y, 4 * lane + 0)];
        float2 c1 = tile[sidxAC(y, 4 * lane + 1)];
        float2 c2 = tile[sidxAC(y, 4 * lane + 2)];
        float2 c3 = tile[sidxAC(y, 4 * lane + 3)];
        float4* dst = (float4*)(&g_Z[base + (size_t)y * VDIM + 4 * lane]);
        dst[0] = make_float4(c0.x, c0.y, c1.x, c1.y);
        dst[1] = make_float4(c2.x, c2.y, c3.x, c3.y);
    }
}

__device__ __forceinline__ float2 Hval(float2 Z, float2 Zn) {
    const float px = Z.x + Zn.x, py = Z.y - Zn.y;   // 2*F1
    const float qx = Z.x - Zn.x, qy = Z.y + Zn.y;   // 2i*F2
    return make_float2(0.25f * (px * qy - py * qx),
                       0.25f * (px * qx + py * qy));
}

// Pass B: forward z-FFT + pointwise H (Hermitian pairing) + inverse z-FFT, fused.
// Lane map puts 16 consecutive x-points in each gmem instruction (2 wf/instr).
__global__ __launch_bounds__(512) void passB() {
    extern __shared__ float2 sm[];
    float2* tile = sm;                              // 64 lines x 128 (z)
    float2* tw = sm + 64 * 128; float2* tw4 = tw + 64; float2* tw8 = tw4 + 16;
    const int xt = blockIdx.x, jy = blockIdx.y, b = blockIdx.z;
    const int jy2 = bneg7(jy);
    const int xt2 = (xt < 2) ? xt : (5 - xt);
    if (jy2 < jy || (jy2 == jy && xt2 < xt)) return;
    init_tw(tw, tw4, tw8);
    const int tid = threadIdx.x;
    const int t = (tid >> 4) & 7;
    const int l = ((tid >> 7) << 4) | (tid & 15);
    const int xi = l & 31;
    const int gx = (l < 32) ? (32 * xt + xi) : (32 * xt2 + xi);
    const int gy = (l < 32) ? jy : jy2;
    const size_t gb = (size_t)b * VOL + (size_t)gy * VDIM + gx;
    float2 r[16];
    __syncthreads();
    #pragma unroll
    for (int j = 0; j < 16; ++j) r[j] = g_Z[gb + (size_t)(t + 8 * j) * SLAB];
    fftA_fwd(r, t, tw, tw4, tw8);
    #pragma unroll
    for (int j = 0; j < 16; ++j) tile[sidxB(l, t + 8 * j)] = r[j];
    __syncthreads();
    #pragma unroll
    for (int m = 0; m < 16; ++m) r[m] = tile[sidxB(l, 16 * t + m)];
    fftB_fwd(r, tw);
    #pragma unroll
    for (int m = 0; m < 16; ++m) tile[sidxB(l, 16 * t + m)] = r[m];
    __syncthreads();
    // pointwise: warp spans 32 consecutive jz; read-all / sync / write-all
    {
        const int jz = tid & 127, row0 = tid >> 7;
        const int jzn = bneg7(jz);
        #pragma unroll
        for (int k = 0; k < 16; ++k) {
            const int row = row0 + 4 * k;
            const int pr = (row < 32) ? (32 + bneg7(32 * xt + row) - 32 * xt2)
                                      : (bneg7(32 * xt2 + (row - 32)) - 32 * xt);
            r[k] = Hval(tile[sidxB(row, jz)], tile[sidxB(pr, jzn)]);
        }
        __syncthreads();
        #pragma unroll
        for (int k = 0; k < 16; ++k) tile[sidxB(row0 + 4 * k, jz)] = r[k];
    }
    __syncthreads();
    #pragma unroll
    for (int m = 0; m < 16; ++m) r[m] = tile[sidxB(l, 16 * t + m)];
    fftB_inv(r, tw);
    #pragma unroll
    for (int m = 0; m < 16; ++m) tile[sidxB(l, 16 * t + m)] = r[m];
    __syncthreads();
    #pragma unroll
    for (int j = 0; j < 16; ++j) r[j] = tile[sidxB(l, t + 8 * j)];
    fftA_inv(r, t, tw, tw4, tw8);
    #pragma unroll
    for (int j = 0; j < 16; ++j) g_Z[gb + (size_t)(t + 8 * j) * SLAB] = r[j];
}

// Pass C: inverse FFT along y then x per slab, write real part / N^3.
__global__ __launch_bounds__(512) void passC(float* __restrict__ out) {
    extern __shared__ float2 sm[];
    float2* tile = sm;
    float2* tw = sm + 128 * 128; float2* tw4 = tw + 64; float2* tw8 = tw4 + 16;
    init_tw(tw, tw4, tw8);
    const int tid = threadIdx.x, w = tid >> 5, lane = tid & 31;
    const int t = lane & 7, q = (lane >> 3) & 1, h = lane >> 4;
    const int B0 = 2 * (w & 7) + 32 * (w >> 3);
    const size_t base = (size_t)blockIdx.x * SLAB;
    const float sc = 1.0f / (float)VOL;
    float2 r[16];
    __syncthreads();
    // copy-in: 8 coalesced g_Z rows per warp
    #pragma unroll
    for (int c8 = 0; c8 < 8; ++c8) {
        const int y = B0 + 16 * (c8 & 1) + ((c8 >> 1) & 1) + 64 * (c8 >> 2);
        const float4* src = (const float4*)(&g_Z[base + (size_t)y * VDIM + 4 * lane]);
        const float4 d0 = src[0], d1 = src[1];
        tile[sidxAC(y, 4 * lane + 0)] = make_float2(d0.x, d0.y);
        tile[sidxAC(y, 4 * lane + 1)] = make_float2(d0.z, d0.w);
        tile[sidxAC(y, 4 * lane + 2)] = make_float2(d1.x, d1.y);
        tile[sidxAC(y, 4 * lane + 3)] = make_float2(d1.z, d1.w);
    }
    __syncthreads();
    #pragma unroll 1
    for (int rep = 0; rep < 2; ++rep) {            // y-dim, pattern B
        const int x = B0 + q + 16 * h + 64 * rep;
        #pragma unroll
        for (int m = 0; m < 16; ++m) r[m] = tile[sidxAC(16 * t + m, x)];
        fftB_inv(r, tw);
        #pragma unroll
        for (int m = 0; m < 16; ++m) tile[sidxAC(16 * t + m, x)] = r[m];
    }
    __syncwarp();
    #pragma unroll 1
    for (int rep = 0; rep < 2; ++rep) {            // y-dim, pattern A
        const int x = B0 + 16 * q + h + 64 * rep;
        #pragma unroll
        for (int j = 0; j < 16; ++j) r[j] = tile[sidxAC(t + 8 * j, x)];
        fftA_inv(r, t, tw, tw4, tw8);
        #pragma unroll
        for (int j = 0; j < 16; ++j) tile[sidxAC(t + 8 * j, x)] = r[j];
    }
    __syncthreads();
    #pragma unroll 1
    for (int rep = 0; rep < 2; ++rep) {            // x-dim, pattern B
        const int y = B0 + q + 16 * h + 64 * rep;
        #pragma unroll
        for (int m = 0; m < 16; ++m) r[m] = tile[sidxAC(y, 16 * t + m)];
        fftB_inv(r, tw);
        #pragma unroll
        for (int m = 0; m < 16; ++m) tile[sidxAC(y, 16 * t + m)] = r[m];
    }
    __syncwarp();
    #pragma unroll 1
    for (int rep = 0; rep < 2; ++rep) {            // x-dim, pattern A -> out
        const int y = B0 + 16 * q + h + 64 * rep;
        #pragma unroll
        for (int j = 0; j < 16; ++j) r[j] = tile[sidxAC(y, t + 8 * j)];
        fftA_inv(r, t, tw, tw4, tw8);
        #pragma unroll
        for (int j = 0; j < 16; ++j) out[base + y * VDIM + t + 8 * j] = r[j].x * sc;
    }
}

extern "C" void kernel_launch(void* const* d_in, const int* in_sizes, int n_in,
                              void* d_out, int out_size) {
    const float* v1 = (const float*)d_in[0];
    const float* v2 = (const float*)d_in[1];
    float* out = (float*)d_out;
    const int smAC = (128 * 128 + 64 + 16 + 8) * (int)sizeof(float2);  // 131,776 B
    const int smB  = (64 * 128 + 64 + 16 + 8) * (int)sizeof(float2);   //  66,240 B
    cudaFuncSetAttribute(passA, cudaFuncAttributeMaxDynamicSharedMemorySize, smAC);
    cudaFuncSetAttribute(passC, cudaFuncAttributeMaxDynamicSharedMemorySize, smAC);
    cudaFuncSetAttribute(passB, cudaFuncAttributeMaxDynamicSharedMemorySize, smB);
    passA<<<NB * VDIM, 512, smAC>>>(v1, v2);
    passB<<<dim3(4, VDIM, NB), 512, smB>>>();
    passC<<<NB * VDIM, 512, smAC>>>(out);
}

// round 5
// speedup vs baseline: 1.6434x; 1.6434x over previous
#include <cuda_runtime.h>

#define VDIM 128
#define NB   8
#define SLAB 16384
#define VOL  2097152

// Scratch spectrum: 8 * 128^3 complex = 134 MB (static device alloc allowed).
__device__ float2 g_Z[(size_t)NB * VOL];

__device__ __forceinline__ int brev7(int x) { return (int)(__brev((unsigned)x) >> 25); }
__device__ __forceinline__ int bneg7(int j) {
    int k = brev7(j); k = (VDIM - k) & 127; return brev7(k);
}

// passA/C tile swizzle (row stride 128; XOR spread), conflict-free for all phases.
__device__ __forceinline__ int sidxAC(int y, int x) {
    int c = x ^ ((x >> 4) & 7) ^ ((x & 1) << 3)
              ^ (y & 7) ^ ((y >> 4) & 7) ^ ((y & 1) << 3);
    return (y << 7) + c;
}
// passB tile swizzle for lane map t=(tid>>4)&7, l=(tid>>7)<<4|(tid&15).
__device__ __forceinline__ int sidxB(int l, int z) {
    int c = z ^ ((z >> 4) & 7) ^ (l & 15);
    return (l << 7) + c;
}

__device__ __forceinline__ float2 cmul(float2 a, float2 w) {
    return make_float2(a.x * w.x - a.y * w.y, a.x * w.y + a.y * w.x);
}
__device__ __forceinline__ float2 cmulc(float2 a, float2 w) {
    return make_float2(a.x * w.x + a.y * w.y, a.y * w.x - a.x * w.y);
}
__device__ __forceinline__ void bf_fwd(float2& ra, float2& rb, float2 w) {
    float2 a = ra, b = rb;
    ra = make_float2(a.x + b.x, a.y + b.y);
    rb = cmul(make_float2(a.x - b.x, a.y - b.y), w);
}
__device__ __forceinline__ void bf_inv(float2& ra, float2& rb, float2 w) {
    float2 a = ra, t = cmulc(rb, w);
    ra = make_float2(a.x + t.x, a.y + t.y);
    rb = make_float2(a.x - t.x, a.y - t.y);
}

// Pattern A: r[j] = x[t + 8j].  Forward DIF stages half = 64,32,16,8.
__device__ __forceinline__ void fftA_fwd(float2 r[16], int t, const float2* tw,
                                         const float2* tw4, const float2* tw8) {
    #pragma unroll
    for (int j = 0; j < 8; ++j) bf_fwd(r[j], r[j + 8], tw[t + 8 * j]);
    #pragma unroll
    for (int g = 0; g < 8; ++g) { int j = ((g & ~3) << 1) | (g & 3); bf_fwd(r[j], r[j + 4], tw[2 * (t + 8 * (j & 3))]); }
    #pragma unroll
    for (int g = 0; g < 8; ++g) { int j = ((g & ~1) << 1) | (g & 1); bf_fwd(r[j], r[j + 2], tw4[t + 8 * (j & 1)]); }
    #pragma unroll
    for (int g = 0; g < 8; ++g) { int j = 2 * g; bf_fwd(r[j], r[j + 1], tw8[t]); }
}
__device__ __forceinline__ void fftA_inv(float2 r[16], int t, const float2* tw,
                                         const float2* tw4, const float2* tw8) {
    #pragma unroll
    for (int g = 0; g < 8; ++g) { int j = 2 * g; bf_inv(r[j], r[j + 1], tw8[t]); }
    #pragma unroll
    for (int g = 0; g < 8; ++g) { int j = ((g & ~1) << 1) | (g & 1); bf_inv(r[j], r[j + 2], tw4[t + 8 * (j & 1)]); }
    #pragma unroll
    for (int g = 0; g < 8; ++g) { int j = ((g & ~3) << 1) | (g & 3); bf_inv(r[j], r[j + 4], tw[2 * (t + 8 * (j & 3))]); }
    #pragma unroll
    for (int j = 0; j < 8; ++j) bf_inv(r[j], r[j + 8], tw[t + 8 * j]);
}
// Pattern B: r[m] = x[16u + m].  Forward DIF stages half = 4,2,1.
__device__ __forceinline__ void fftB_fwd(float2 r[16], const float2* tw) {
    #pragma unroll
    for (int g = 0; g < 8; ++g) { int m = ((g & ~3) << 1) | (g & 3); bf_fwd(r[m], r[m + 4], tw[(m & 3) << 4]); }
    #pragma unroll
    for (int g = 0; g < 8; ++g) { int m = ((g & ~1) << 1) | (g & 1); bf_fwd(r[m], r[m + 2], tw[(m & 1) << 5]); }
    #pragma unroll
    for (int g = 0; g < 8; ++g) {
        int m = 2 * g; float2 a = r[m], b = r[m + 1];
        r[m] = make_float2(a.x + b.x, a.y + b.y);
        r[m + 1] = make_float2(a.x - b.x, a.y - b.y);
    }
}
__device__ __forceinline__ void fftB_inv(float2 r[16], const float2* tw) {
    #pragma unroll
    for (int g = 0; g < 8; ++g) {
        int m = 2 * g; float2 a = r[m], b = r[m + 1];
        r[m] = make_float2(a.x + b.x, a.y + b.y);
        r[m + 1] = make_float2(a.x - b.x, a.y - b.y);
    }
    #pragma unroll
    for (int g = 0; g < 8; ++g) { int m = ((g & ~1) << 1) | (g & 1); bf_inv(r[m], r[m + 2], tw[(m & 1) << 5]); }
    #pragma unroll
    for (int g = 0; g < 8; ++g) { int m = ((g & ~3) << 1) | (g & 3); bf_inv(r[m], r[m + 4], tw[(m & 3) << 4]); }
}

__device__ __forceinline__ void init_tw(float2* tw, float2* tw4, float2* tw8) {
    for (int i = threadIdx.x; i < 64; i += blockDim.x) {
        float sn, cs; sincospif(i * (1.0f / 64.0f), &sn, &cs);
        float2 w = make_float2(cs, -sn);
        tw[i] = w;
        if (!(i & 3)) tw4[i >> 2] = w;
        if (!(i & 7)) tw8[i >> 3] = w;
    }
}

// Pass A: pack v1 + i*v2, forward FFT along x then y per (b,z) slab.
__global__ __launch_bounds__(512) void passA(const float* __restrict__ v1,
                                             const float* __restrict__ v2) {
    extern __shared__ float2 sm[];
    float2* tile = sm;
    float2* tw = sm + 128 * 128; float2* tw4 = tw + 64; float2* tw8 = tw4 + 16;
    init_tw(tw, tw4, tw8);
    const int tid = threadIdx.x, w = tid >> 5, lane = tid & 31;
    const int t = lane & 7, q = (lane >> 3) & 1, h = lane >> 4;
    const int B0 = 2 * (w & 7) + 32 * (w >> 3);
    const int t2 = w & 7, xc = 32 * (w >> 3) + lane;   // map for y-dim B (gmem)
    const size_t base = (size_t)blockIdx.x * SLAB;
    float2 r[16];
    __syncthreads();
    #pragma unroll 1
    for (int rep = 0; rep < 2; ++rep) {            // x-dim, pattern A (gmem in)
        const int y = B0 + 16 * q + h + 64 * rep;
        const float* p1 = v1 + base + y * VDIM;
        const float* p2 = v2 + base + y * VDIM;
        #pragma unroll
        for (int j = 0; j < 16; ++j) r[j] = make_float2(p1[t + 8 * j], p2[t + 8 * j]);
        fftA_fwd(r, t, tw, tw4, tw8);
        #pragma unroll
        for (int j = 0; j < 16; ++j) tile[sidxAC(y, t + 8 * j)] = r[j];
    }
    __syncwarp();
    #pragma unroll 1
    for (int rep = 0; rep < 2; ++rep) {            // x-dim, pattern B
        const int y = B0 + q + 16 * h + 64 * rep;
        #pragma unroll
        for (int m = 0; m < 16; ++m) r[m] = tile[sidxAC(y, 16 * t + m)];
        fftB_fwd(r, tw);
        #pragma unroll
        for (int m = 0; m < 16; ++m) tile[sidxAC(y, 16 * t + m)] = r[m];
    }
    __syncthreads();
    #pragma unroll 1
    for (int rep = 0; rep < 2; ++rep) {            // y-dim, pattern A
        const int x = B0 + 16 * q + h + 64 * rep;
        #pragma unroll
        for (int j = 0; j < 16; ++j) r[j] = tile[sidxAC(t + 8 * j, x)];
        fftA_fwd(r, t, tw, tw4, tw8);
        #pragma unroll
        for (int j = 0; j < 16; ++j) tile[sidxAC(t + 8 * j, x)] = r[j];
    }
    __syncthreads();                                // cross-warp line handoff
    #pragma unroll 1
    for (int rep = 0; rep < 2; ++rep) {            // y-dim, pattern B (coalesced gmem out)
        const int x = xc + 64 * rep;
        #pragma unroll
        for (int m = 0; m < 16; ++m) r[m] = tile[sidxAC(16 * t2 + m, x)];
        fftB_fwd(r, tw);
        #pragma unroll
        for (int m = 0; m < 16; ++m) g_Z[base + (size_t)(16 * t2 + m) * VDIM + x] = r[m];
    }
}

__device__ __forceinline__ float2 Hval(float2 Z, float2 Zn) {
    const float px = Z.x + Zn.x, py = Z.y - Zn.y;   // 2*F1
    const float qx = Z.x - Zn.x, qy = Z.y + Zn.y;   // 2i*F2
    return make_float2(0.25f * (px * qy - py * qx),
                       0.25f * (px * qx + py * qy));
}

// Pass B: forward z-FFT + pointwise H (Hermitian pairing) + inverse z-FFT, fused.
// Lane map: 16 consecutive x per gmem instruction -> 2 wavefronts/instr.
__global__ __launch_bounds__(512) void passB() {
    extern __shared__ float2 sm[];
    float2* tile = sm;                              // 64 lines x 128 (z)
    float2* tw = sm + 64 * 128; float2* tw4 = tw + 64; float2* tw8 = tw4 + 16;
    const int xt = blockIdx.x, jy = blockIdx.y, b = blockIdx.z;
    const int jy2 = bneg7(jy);
    const int xt2 = (xt < 2) ? xt : (5 - xt);
    if (jy2 < jy || (jy2 == jy && xt2 < xt)) return;
    init_tw(tw, tw4, tw8);
    const int tid = threadIdx.x;
    const int t = (tid >> 4) & 7;
    const int l = ((tid >> 7) << 4) | (tid & 15);
    const int xi = l & 31;
    const int gx = (l < 32) ? (32 * xt + xi) : (32 * xt2 + xi);
    const int gy = (l < 32) ? jy : jy2;
    const size_t gb = (size_t)b * VOL + (size_t)gy * VDIM + gx;
    float2 r[16];
    __syncthreads();
    #pragma unroll
    for (int j = 0; j < 16; ++j) r[j] = g_Z[gb + (size_t)(t + 8 * j) * SLAB];
    fftA_fwd(r, t, tw, tw4, tw8);
    #pragma unroll
    for (int j = 0; j < 16; ++j) tile[sidxB(l, t + 8 * j)] = r[j];
    __syncthreads();
    #pragma unroll
    for (int m = 0; m < 16; ++m) r[m] = tile[sidxB(l, 16 * t + m)];
    fftB_fwd(r, tw);
    #pragma unroll
    for (int m = 0; m < 16; ++m) tile[sidxB(l, 16 * t + m)] = r[m];
    __syncthreads();
    // pointwise: warp spans 32 consecutive jz; read-all / sync / write-all
    {
        const int jz = tid & 127, row0 = tid >> 7;
        const int jzn = bneg7(jz);
        #pragma unroll
        for (int k = 0; k < 16; ++k) {
            const int row = row0 + 4 * k;
            const int pr = (row < 32) ? (32 + bneg7(32 * xt + row) - 32 * xt2)
                                      : (bneg7(32 * xt2 + (row - 32)) - 32 * xt);
            r[k] = Hval(tile[sidxB(row, jz)], tile[sidxB(pr, jzn)]);
        }
        __syncthreads();
        #pragma unroll
        for (int k = 0; k < 16; ++k) tile[sidxB(row0 + 4 * k, jz)] = r[k];
    }
    __syncthreads();
    #pragma unroll
    for (int m = 0; m < 16; ++m) r[m] = tile[sidxB(l, 16 * t + m)];
    fftB_inv(r, tw);
    #pragma unroll
    for (int m = 0; m < 16; ++m) tile[sidxB(l, 16 * t + m)] = r[m];
    __syncthreads();
    #pragma unroll
    for (int j = 0; j < 16; ++j) r[j] = tile[sidxB(l, t + 8 * j)];
    fftA_inv(r, t, tw, tw4, tw8);
    #pragma unroll
    for (int j = 0; j < 16; ++j) g_Z[gb + (size_t)(t + 8 * j) * SLAB] = r[j];
}

// Pass C: inverse FFT along y then x per slab, write real part / N^3.
__global__ __launch_bounds__(512) void passC(float* __restrict__ out) {
    extern __shared__ float2 sm[];
    float2* tile = sm;
    float2* tw = sm + 128 * 128; float2* tw4 = tw + 64; float2* tw8 = tw4 + 16;
    init_tw(tw, tw4, tw8);
    const int tid = threadIdx.x, w = tid >> 5, lane = tid & 31;
    const int t = lane & 7, q = (lane >> 3) & 1, h = lane >> 4;
    const int B0 = 2 * (w & 7) + 32 * (w >> 3);
    const int t2 = w & 7, xc = 32 * (w >> 3) + lane;   // map for y-dim B (gmem)
    const size_t base = (size_t)blockIdx.x * SLAB;
    const float sc = 1.0f / (float)VOL;
    float2 r[16];
    __syncthreads();
    #pragma unroll 1
    for (int rep = 0; rep < 2; ++rep) {            // y-dim, pattern B (coalesced gmem in)
        const int x = xc + 64 * rep;
        #pragma unroll
        for (int m = 0; m < 16; ++m) r[m] = g_Z[base + (size_t)(16 * t2 + m) * VDIM + x];
        fftB_inv(r, tw);
        #pragma unroll
        for (int m = 0; m < 16; ++m) tile[sidxAC(16 * t2 + m, x)] = r[m];
    }
    __syncthreads();
    #pragma unroll 1
    for (int rep = 0; rep < 2; ++rep) {            // y-dim, pattern A
        const int x = B0 + 16 * q + h + 64 * rep;
        #pragma unroll
        for (int j = 0; j < 16; ++j) r[j] = tile[sidxAC(t + 8 * j, x)];
        fftA_inv(r, t, tw, tw4, tw8);
        #pragma unroll
        for (int j = 0; j < 16; ++j) tile[sidxAC(t + 8 * j, x)] = r[j];
    }
    __syncthreads();
    #pragma unroll 1
    for (int rep = 0; rep < 2; ++rep) {            // x-dim, pattern B
        const int y = B0 + q + 16 * h + 64 * rep;
        #pragma unroll
        for (int m = 0; m < 16; ++m) r[m] = tile[sidxAC(y, 16 * t + m)];
        fftB_inv(r, tw);
        #pragma unroll
        for (int m = 0; m < 16; ++m) tile[sidxAC(y, 16 * t + m)] = r[m];
    }
    __syncwarp();
    #pragma unroll 1
    for (int rep = 0; rep < 2; ++rep) {            // x-dim, pattern A -> out
        const int y = B0 + 16 * q + h + 64 * rep;
        #pragma unroll
        for (int j = 0; j < 16; ++j) r[j] = tile[sidxAC(y, t + 8 * j)];
        fftA_inv(r, t, tw, tw4, tw8);
        #pragma unroll
        for (int j = 0; j < 16; ++j) out[base + y * VDIM + t + 8 * j] = r[j].x * sc;
    }
}

extern "C" void kernel_launch(void* const* d_in, const int* in_sizes, int n_in,
                              void* d_out, int out_size) {
    const float* v1 = (const float*)d_in[0];
    const float* v2 = (const float*)d_in[1];
    float* out = (float*)d_out;
    const int smAC = (128 * 128 + 64 + 16 + 8) * (int)sizeof(float2);  // 131,776 B
    const int smB  = (64 * 128 + 64 + 16 + 8) * (int)sizeof(float2);   //  66,240 B
    cudaFuncSetAttribute(passA, cudaFuncAttributeMaxDynamicSharedMemorySize, smAC);
    cudaFuncSetAttribute(passC, cudaFuncAttributeMaxDynamicSharedMemorySize, smAC);
    cudaFuncSetAttribute(passB, cudaFuncAttributeMaxDynamicSharedMemorySize, smB);
    passA<<<NB * VDIM, 512, smAC>>>(v1, v2);
    passB<<<dim3(4, VDIM, NB), 512, smB>>>();
    passC<<<NB * VDIM, 512, smAC>>>(out);
}

// round 6
// speedup vs baseline: 1.7578x; 1.0696x over previous
#include <cuda_runtime.h>

#define VDIM 128
#define NB   8
#define SLAB 16384
#define VOL  2097152

// Scratch spectrum: 8 * 128^3 complex = 134 MB (static device alloc allowed).
__device__ float2 g_Z[(size_t)NB * VOL];

__device__ __forceinline__ int brev7(int x) { return (int)(__brev((unsigned)x) >> 25); }
__device__ __forceinline__ int bneg7(int j) {
    int k = brev7(j); k = (VDIM - k) & 127; return brev7(k);
}

// passA/C tile swizzle (row stride 128; XOR spread), conflict-free for all phases.
__device__ __forceinline__ int sidxAC(int y, int x) {
    int c = x ^ ((x >> 4) & 7) ^ ((x & 1) << 3)
              ^ (y & 7) ^ ((y >> 4) & 7) ^ ((y & 1) << 3);
    return (y << 7) + c;
}
// passB tile swizzle for lane map t=(tid>>4)&7, l=(tid>>7)<<4|(tid&15).
__device__ __forceinline__ int sidxB(int l, int z) {
    int c = z ^ ((z >> 4) & 7) ^ (l & 15);
    return (l << 7) + c;
}

__device__ __forceinline__ float2 cmul(float2 a, float2 w) {
    return make_float2(a.x * w.x - a.y * w.y, a.x * w.y + a.y * w.x);
}
__device__ __forceinline__ float2 cmulc(float2 a, float2 w) {
    return make_float2(a.x * w.x + a.y * w.y, a.y * w.x - a.x * w.y);
}
__device__ __forceinline__ void bf_fwd(float2& ra, float2& rb, float2 w) {
    float2 a = ra, b = rb;
    ra = make_float2(a.x + b.x, a.y + b.y);
    rb = cmul(make_float2(a.x - b.x, a.y - b.y), w);
}
__device__ __forceinline__ void bf_inv(float2& ra, float2& rb, float2 w) {
    float2 a = ra, t = cmulc(rb, w);
    ra = make_float2(a.x + t.x, a.y + t.y);
    rb = make_float2(a.x - t.x, a.y - t.y);
}

// Pattern A: r[j] = x[t + 8j].  Forward DIF stages half = 64,32,16,8.
__device__ __forceinline__ void fftA_fwd(float2 r[16], int t, const float2* tw,
                                         const float2* tw4, const float2* tw8) {
    #pragma unroll
    for (int j = 0; j < 8; ++j) bf_fwd(r[j], r[j + 8], tw[t + 8 * j]);
    #pragma unroll
    for (int g = 0; g < 8; ++g) { int j = ((g & ~3) << 1) | (g & 3); bf_fwd(r[j], r[j + 4], tw[2 * (t + 8 * (j & 3))]); }
    #pragma unroll
    for (int g = 0; g < 8; ++g) { int j = ((g & ~1) << 1) | (g & 1); bf_fwd(r[j], r[j + 2], tw4[t + 8 * (j & 1)]); }
    #pragma unroll
    for (int g = 0; g < 8; ++g) { int j = 2 * g; bf_fwd(r[j], r[j + 1], tw8[t]); }
}
__device__ __forceinline__ void fftA_inv(float2 r[16], int t, const float2* tw,
                                         const float2* tw4, const float2* tw8) {
    #pragma unroll
    for (int g = 0; g < 8; ++g) { int j = 2 * g; bf_inv(r[j], r[j + 1], tw8[t]); }
    #pragma unroll
    for (int g = 0; g < 8; ++g) { int j = ((g & ~1) << 1) | (g & 1); bf_inv(r[j], r[j + 2], tw4[t + 8 * (j & 1)]); }
    #pragma unroll
    for (int g = 0; g < 8; ++g) { int j = ((g & ~3) << 1) | (g & 3); bf_inv(r[j], r[j + 4], tw[2 * (t + 8 * (j & 3))]); }
    #pragma unroll
    for (int j = 0; j < 8; ++j) bf_inv(r[j], r[j + 8], tw[t + 8 * j]);
}
// Pattern B: r[m] = x[16u + m].  Forward DIF stages half = 4,2,1.
__device__ __forceinline__ void fftB_fwd(float2 r[16], const float2* tw) {
    #pragma unroll
    for (int g = 0; g < 8; ++g) { int m = ((g & ~3) << 1) | (g & 3); bf_fwd(r[m], r[m + 4], tw[(m & 3) << 4]); }
    #pragma unroll
    for (int g = 0; g < 8; ++g) { int m = ((g & ~1) << 1) | (g & 1); bf_fwd(r[m], r[m + 2], tw[(m & 1) << 5]); }
    #pragma unroll
    for (int g = 0; g < 8; ++g) {
        int m = 2 * g; float2 a = r[m], b = r[m + 1];
        r[m] = make_float2(a.x + b.x, a.y + b.y);
        r[m + 1] = make_float2(a.x - b.x, a.y - b.y);
    }
}
__device__ __forceinline__ void fftB_inv(float2 r[16], const float2* tw) {
    #pragma unroll
    for (int g = 0; g < 8; ++g) {
        int m = 2 * g; float2 a = r[m], b = r[m + 1];
        r[m] = make_float2(a.x + b.x, a.y + b.y);
        r[m + 1] = make_float2(a.x - b.x, a.y - b.y);
    }
    #pragma unroll
    for (int g = 0; g < 8; ++g) { int m = ((g & ~1) << 1) | (g & 1); bf_inv(r[m], r[m + 2], tw[(m & 1) << 5]); }
    #pragma unroll
    for (int g = 0; g < 8; ++g) { int m = ((g & ~3) << 1) | (g & 3); bf_inv(r[m], r[m + 4], tw[(m & 3) << 4]); }
}

__device__ __forceinline__ void init_tw(float2* tw, float2* tw4, float2* tw8) {
    for (int i = threadIdx.x; i < 64; i += blockDim.x) {
        float sn, cs; sincospif(i * (1.0f / 64.0f), &sn, &cs);
        float2 w = make_float2(cs, -sn);
        tw[i] = w;
        if (!(i & 3)) tw4[i >> 2] = w;
        if (!(i & 7)) tw8[i >> 3] = w;
    }
}

// Pass A: pack v1 + i*v2, forward FFT along x then y per (b,z) slab.
__global__ __launch_bounds__(512) void passA(const float* __restrict__ v1,
                                             const float* __restrict__ v2) {
    extern __shared__ float2 sm[];
    float2* tile = sm;
    float2* tw = sm + 128 * 128; float2* tw4 = tw + 64; float2* tw8 = tw4 + 16;
    init_tw(tw, tw4, tw8);
    const int tid = threadIdx.x, w = tid >> 5, lane = tid & 31;
    const int t = lane & 7, q = (lane >> 3) & 1, h = lane >> 4;
    const int B0 = 2 * (w & 7) + 32 * (w >> 3);
    const int t2 = w & 7, xc = 32 * (w >> 3) + lane;   // map for y-dim B (gmem)
    const size_t base = (size_t)blockIdx.x * SLAB;
    float2 r[16];
    __syncthreads();
    #pragma unroll 1
    for (int rep = 0; rep < 2; ++rep) {            // x-dim, pattern A (gmem in)
        const int y = B0 + 16 * q + h + 64 * rep;
        const float* p1 = v1 + base + y * VDIM;
        const float* p2 = v2 + base + y * VDIM;
        #pragma unroll
        for (int j = 0; j < 16; ++j) r[j] = make_float2(p1[t + 8 * j], p2[t + 8 * j]);
        fftA_fwd(r, t, tw, tw4, tw8);
        #pragma unroll
        for (int j = 0; j < 16; ++j) tile[sidxAC(y, t + 8 * j)] = r[j];
    }
    __syncwarp();
    #pragma unroll 1
    for (int rep = 0; rep < 2; ++rep) {            // x-dim, pattern B
        const int y = B0 + q + 16 * h + 64 * rep;
        #pragma unroll
        for (int m = 0; m < 16; ++m) r[m] = tile[sidxAC(y, 16 * t + m)];
        fftB_fwd(r, tw);
        #pragma unroll
        for (int m = 0; m < 16; ++m) tile[sidxAC(y, 16 * t + m)] = r[m];
    }
    __syncthreads();
    #pragma unroll 1
    for (int rep = 0; rep < 2; ++rep) {            // y-dim, pattern A
        const int x = B0 + 16 * q + h + 64 * rep;
        #pragma unroll
        for (int j = 0; j < 16; ++j) r[j] = tile[sidxAC(t + 8 * j, x)];
        fftA_fwd(r, t, tw, tw4, tw8);
        #pragma unroll
        for (int j = 0; j < 16; ++j) tile[sidxAC(t + 8 * j, x)] = r[j];
    }
    __syncthreads();
    #pragma unroll 1
    for (int rep = 0; rep < 2; ++rep) {            // y-dim, pattern B (coalesced out)
        const int x = xc + 64 * rep;
        #pragma unroll
        for (int m = 0; m < 16; ++m) r[m] = tile[sidxAC(16 * t2 + m, x)];
        fftB_fwd(r, tw);
        #pragma unroll
        for (int m = 0; m < 16; ++m) g_Z[base + (size_t)(16 * t2 + m) * VDIM + x] = r[m];
    }
}

__device__ __forceinline__ float2 Hval(float2 Z, float2 Zn) {
    const float px = Z.x + Zn.x, py = Z.y - Zn.y;   // 2*F1
    const float qx = Z.x - Zn.x, qy = Z.y + Zn.y;   // 2i*F2
    return make_float2(0.25f * (px * qy - py * qx),
                       0.25f * (px * qx + py * qy));
}

// Pass B: forward z-FFT + pointwise H + inverse z-FFT, fused.
// Hermitian: H(-k)=conj(H(k)) survives inverse-z at the same z, so only
// tileA (rows jy<jy2, all xt; plus self rows fully) is inverted and stored.
__global__ __launch_bounds__(512) void passB() {
    extern __shared__ float2 sm[];
    float2* tile = sm;                              // 64 lines x 128 (z)
    float2* tw = sm + 64 * 128; float2* tw4 = tw + 64; float2* tw8 = tw4 + 16;
    const int xt = blockIdx.x, jy = blockIdx.y, b = blockIdx.z;
    const int jy2 = bneg7(jy);
    const int xt2 = (xt < 2) ? xt : (5 - xt);
    if (jy2 < jy || (jy2 == jy && xt2 < xt)) return;
    const bool full = (jy2 == jy);                  // self rows: store both tiles
    init_tw(tw, tw4, tw8);
    const int tid = threadIdx.x;
    const int t = (tid >> 4) & 7;
    const int l = ((tid >> 7) << 4) | (tid & 15);
    const int xi = l & 31;
    const int gx = (l < 32) ? (32 * xt + xi) : (32 * xt2 + xi);
    const int gy = (l < 32) ? jy : jy2;
    const size_t gb = (size_t)b * VOL + (size_t)gy * VDIM + gx;
    float2 r[16];
    __syncthreads();
    #pragma unroll
    for (int j = 0; j < 16; ++j) r[j] = g_Z[gb + (size_t)(t + 8 * j) * SLAB];
    fftA_fwd(r, t, tw, tw4, tw8);
    #pragma unroll
    for (int j = 0; j < 16; ++j) tile[sidxB(l, t + 8 * j)] = r[j];
    __syncthreads();
    #pragma unroll
    for (int m = 0; m < 16; ++m) r[m] = tile[sidxB(l, 16 * t + m)];
    fftB_fwd(r, tw);
    #pragma unroll
    for (int m = 0; m < 16; ++m) tile[sidxB(l, 16 * t + m)] = r[m];
    __syncthreads();
    // pointwise: warp spans 32 consecutive jz; read-all / sync / write-all
    {
        const int jz = tid & 127, row0 = tid >> 7;
        const int jzn = bneg7(jz);
        #pragma unroll
        for (int k = 0; k < 16; ++k) {
            const int row = row0 + 4 * k;
            const int pr = (row < 32) ? (32 + bneg7(32 * xt + row) - 32 * xt2)
                                      : (bneg7(32 * xt2 + (row - 32)) - 32 * xt);
            r[k] = Hval(tile[sidxB(row, jz)], tile[sidxB(pr, jzn)]);
        }
        __syncthreads();
        #pragma unroll
        for (int k = 0; k < 16; ++k) tile[sidxB(row0 + 4 * k, jz)] = r[k];
    }
    __syncthreads();
    if (full || l < 32) {
        #pragma unroll
        for (int m = 0; m < 16; ++m) r[m] = tile[sidxB(l, 16 * t + m)];
        fftB_inv(r, tw);
        #pragma unroll
        for (int m = 0; m < 16; ++m) tile[sidxB(l, 16 * t + m)] = r[m];
    }
    __syncthreads();
    if (full || l < 32) {
        #pragma unroll
        for (int j = 0; j < 16; ++j) r[j] = tile[sidxB(l, t + 8 * j)];
        fftA_inv(r, t, tw, tw4, tw8);
        #pragma unroll
        for (int j = 0; j < 16; ++j) g_Z[gb + (size_t)(t + 8 * j) * SLAB] = r[j];
    }
}

// Pass C: gather the stored half-spectrum, mirror-fill conj half in smem,
// inverse FFT along y then x per slab, write real part / N^3.
__global__ __launch_bounds__(512) void passC(float* __restrict__ out) {
    extern __shared__ float2 sm[];
    float2* tile = sm;
    float2* tw = sm + 128 * 128; float2* tw4 = tw + 64; float2* tw8 = tw4 + 16;
    init_tw(tw, tw4, tw8);
    const int tid = threadIdx.x, w = tid >> 5, lane = tid & 31;
    const int t = lane & 7, q = (lane >> 3) & 1, h = lane >> 4;
    const int B0 = 2 * (w & 7) + 32 * (w >> 3);
    const int t2 = w & 7, xc = 32 * (w >> 3) + lane;
    const size_t base = (size_t)blockIdx.x * SLAB;
    const float sc = 1.0f / (float)VOL;
    float2 r[16];
    __syncthreads();
    // gather copy-in: load kept rows (jy <= bneg7(jy)); mirror-fill the rest.
    #pragma unroll 1
    for (int jy = w; jy < 128; jy += 16) {
        const int jy2 = bneg7(jy);
        if (jy > jy2) continue;
        #pragma unroll
        for (int k = 0; k < 4; ++k) {
            const int xx = lane + 32 * k;
            const float2 v = g_Z[base + (size_t)jy * VDIM + xx];
            tile[sidxAC(jy, xx)] = v;
            if (jy2 != jy) tile[sidxAC(jy2, bneg7(xx))] = make_float2(v.x, -v.y);
        }
    }
    __syncthreads();
    #pragma unroll 1
    for (int rep = 0; rep < 2; ++rep) {            // y-dim, pattern B (from smem)
        const int x = xc + 64 * rep;
        #pragma unroll
        for (int m = 0; m < 16; ++m) r[m] = tile[sidxAC(16 * t2 + m, x)];
        fftB_inv(r, tw);
        #pragma unroll
        for (int m = 0; m < 16; ++m) tile[sidxAC(16 * t2 + m, x)] = r[m];
    }
    __syncthreads();
    #pragma unroll 1
    for (int rep = 0; rep < 2; ++rep) {            // y-dim, pattern A
        const int x = B0 + 16 * q + h + 64 * rep;
        #pragma unroll
        for (int j = 0; j < 16; ++j) r[j] = tile[sidxAC(t + 8 * j, x)];
        fftA_inv(r, t, tw, tw4, tw8);
        #pragma unroll
        for (int j = 0; j < 16; ++j) tile[sidxAC(t + 8 * j, x)] = r[j];
    }
    __syncthreads();
    #pragma unroll 1
    for (int rep = 0; rep < 2; ++rep) {            // x-dim, pattern B
        const int y = B0 + q + 16 * h + 64 * rep;
        #pragma unroll
        for (int m = 0; m < 16; ++m) r[m] = tile[sidxAC(y, 16 * t + m)];
        fftB_inv(r, tw);
        #pragma unroll
        for (int m = 0; m < 16; ++m) tile[sidxAC(y, 16 * t + m)] = r[m];
    }
    __syncwarp();
    #pragma unroll 1
    for (int rep = 0; rep < 2; ++rep) {            // x-dim, pattern A -> out
        const int y = B0 + 16 * q + h + 64 * rep;
        #pragma unroll
        for (int j = 0; j < 16; ++j) r[j] = tile[sidxAC(y, t + 8 * j)];
        fftA_inv(r, t, tw, tw4, tw8);
        #pragma unroll
        for (int j = 0; j < 16; ++j) out[base + y * VDIM + t + 8 * j] = r[j].x * sc;
    }
}

extern "C" void kernel_launch(void* const* d_in, const int* in_sizes, int n_in,
                              void* d_out, int out_size) {
    const float* v1 = (const float*)d_in[0];
    const float* v2 = (const float*)d_in[1];
    float* out = (float*)d_out;
    const int smAC = (128 * 128 + 64 + 16 + 8) * (int)sizeof(float2);  // 131,776 B
    const int smB  = (64 * 128 + 64 + 16 + 8) * (int)sizeof(float2);   //  66,240 B
    cudaFuncSetAttribute(passA, cudaFuncAttributeMaxDynamicSharedMemorySize, smAC);
    cudaFuncSetAttribute(passC, cudaFuncAttributeMaxDynamicSharedMemorySize, smAC);
    cudaFuncSetAttribute(passB, cudaFuncAttributeMaxDynamicSharedMemorySize, smB);
    passA<<<NB * VDIM, 512, smAC>>>(v1, v2);
    passB<<<dim3(4, VDIM, NB), 512, smB>>>();
    passC<<<NB * VDIM, 512, smAC>>>(out);
}

// round 8
// speedup vs baseline: 1.8606x; 1.0585x over previous
#include <cuda_runtime.h>
#include <cuda_fp16.h>

#define VDIM 128
#define NB   8
#define SLAB 16384
#define VOL  2097152

// Scratch spectrum stored as half2: 8 * 128^3 * 4 B = 67 MB (static alloc allowed).
__device__ __half2 g_Z[(size_t)NB * VOL];

__device__ __forceinline__ int brev7(int x) { return (int)(__brev((unsigned)x) >> 25); }
__device__ __forceinline__ int bneg7(int j) {
    int k = brev7(j); k = (VDIM - k) & 127; return brev7(k);
}

__device__ __forceinline__ __half2 pack_h2(float2 v) { return __floats2half2_rn(v.x, v.y); }
__device__ __forceinline__ float2 unpack_h2(__half2 h) { return __half22float2(h); }

// passA/C tile swizzle (row stride 128; XOR spread), conflict-free for all phases.
__device__ __forceinline__ int sidxAC(int y, int x) {
    int c = x ^ ((x >> 4) & 7) ^ ((x & 1) << 3)
              ^ (y & 7) ^ ((y >> 4) & 7) ^ ((y & 1) << 3);
    return (y << 7) + c;
}
// passB tile swizzle for lane map t=(tid>>4)&7, l=(tid>>7)<<4|(tid&15).
__device__ __forceinline__ int sidxB(int l, int z) {
    int c = z ^ ((z >> 4) & 7) ^ (l & 15);
    return (l << 7) + c;
}

__device__ __forceinline__ float2 cmul(float2 a, float2 w) {
    return make_float2(a.x * w.x - a.y * w.y, a.x * w.y + a.y * w.x);
}
__device__ __forceinline__ float2 cmulc(float2 a, float2 w) {
    return make_float2(a.x * w.x + a.y * w.y, a.y * w.x - a.x * w.y);
}
__device__ __forceinline__ void bf_fwd(float2& ra, float2& rb, float2 w) {
    float2 a = ra, b = rb;
    ra = make_float2(a.x + b.x, a.y + b.y);
    rb = cmul(make_float2(a.x - b.x, a.y - b.y), w);
}
__device__ __forceinline__ void bf_inv(float2& ra, float2& rb, float2 w) {
    float2 a = ra, t = cmulc(rb, w);
    ra = make_float2(a.x + t.x, a.y + t.y);
    rb = make_float2(a.x - t.x, a.y - t.y);
}

// Pattern A: r[j] = x[t + 8j].  Forward DIF stages half = 64,32,16,8.
__device__ __forceinline__ void fftA_fwd(float2 r[16], int t, const float2* tw,
                                         const float2* tw4, const float2* tw8) {
    #pragma unroll
    for (int j = 0; j < 8; ++j) bf_fwd(r[j], r[j + 8], tw[t + 8 * j]);
    #pragma unroll
    for (int g = 0; g < 8; ++g) { int j = ((g & ~3) << 1) | (g & 3); bf_fwd(r[j], r[j + 4], tw[2 * (t + 8 * (j & 3))]); }
    #pragma unroll
    for (int g = 0; g < 8; ++g) { int j = ((g & ~1) << 1) | (g & 1); bf_fwd(r[j], r[j + 2], tw4[t + 8 * (j & 1)]); }
    #pragma unroll
    for (int g = 0; g < 8; ++g) { int j = 2 * g; bf_fwd(r[j], r[j + 1], tw8[t]); }
}
__device__ __forceinline__ void fftA_inv(float2 r[16], int t, const float2* tw,
                                         const float2* tw4, const float2* tw8) {
    #pragma unroll
    for (int g = 0; g < 8; ++g) { int j = 2 * g; bf_inv(r[j], r[j + 1], tw8[t]); }
    #pragma unroll
    for (int g = 0; g < 8; ++g) { int j = ((g & ~1) << 1) | (g & 1); bf_inv(r[j], r[j + 2], tw4[t + 8 * (j & 1)]); }
    #pragma unroll
    for (int g = 0; g < 8; ++g) { int j = ((g & ~3) << 1) | (g & 3); bf_inv(r[j], r[j + 4], tw[2 * (t + 8 * (j & 3))]); }
    #pragma unroll
    for (int j = 0; j < 8; ++j) bf_inv(r[j], r[j + 8], tw[t + 8 * j]);
}
// Pattern B: r[m] = x[16u + m].  Forward DIF stages half = 4,2,1.
__device__ __forceinline__ void fftB_fwd(float2 r[16], const float2* tw) {
    #pragma unroll
    for (int g = 0; g < 8; ++g) { int m = ((g & ~3) << 1) | (g & 3); bf_fwd(r[m], r[m + 4], tw[(m & 3) << 4]); }
    #pragma unroll
    for (int g = 0; g < 8; ++g) { int m = ((g & ~1) << 1) | (g & 1); bf_fwd(r[m], r[m + 2], tw[(m & 1) << 5]); }
    #pragma unroll
    for (int g = 0; g < 8; ++g) {
        int m = 2 * g; float2 a = r[m], b = r[m + 1];
        r[m] = make_float2(a.x + b.x, a.y + b.y);
        r[m + 1] = make_float2(a.x - b.x, a.y - b.y);
    }
}
__device__ __forceinline__ void fftB_inv(float2 r[16], const float2* tw) {
    #pragma unroll
    for (int g = 0; g < 8; ++g) {
        int m = 2 * g; float2 a = r[m], b = r[m + 1];
        r[m] = make_float2(a.x + b.x, a.y + b.y);
        r[m + 1] = make_float2(a.x - b.x, a.y - b.y);
    }
    #pragma unroll
    for (int g = 0; g < 8; ++g) { int m = ((g & ~1) << 1) | (g & 1); bf_inv(r[m], r[m + 2], tw[(m & 1) << 5]); }
    #pragma unroll
    for (int g = 0; g < 8; ++g) { int m = ((g & ~3) << 1) | (g & 3); bf_inv(r[m], r[m + 4], tw[(m & 3) << 4]); }
}

__device__ __forceinline__ void init_tw(float2* tw, float2* tw4, float2* tw8) {
    for (int i = threadIdx.x; i < 64; i += blockDim.x) {
        float sn, cs; sincospif(i * (1.0f / 64.0f), &sn, &cs);
        float2 w = make_float2(cs, -sn);
        tw[i] = w;
        if (!(i & 3)) tw4[i >> 2] = w;
        if (!(i & 7)) tw8[i >> 3] = w;
    }
}

// Pass A: pack v1 + i*v2, forward FFT along x then y per (b,z) slab.
__global__ __launch_bounds__(512) void passA(const float* __restrict__ v1,
                                             const float* __restrict__ v2) {
    extern __shared__ float2 sm[];
    float2* tile = sm;
    float2* tw = sm + 128 * 128; float2* tw4 = tw + 64; float2* tw8 = tw4 + 16;
    init_tw(tw, tw4, tw8);
    const int tid = threadIdx.x, w = tid >> 5, lane = tid & 31;
    const int t = lane & 7, q = (lane >> 3) & 1, h = lane >> 4;
    const int B0 = 2 * (w & 7) + 32 * (w >> 3);
    const int t2 = w & 7, xc = 32 * (w >> 3) + lane;   // map for y-dim B (gmem)
    const size_t base = (size_t)blockIdx.x * SLAB;
    float2 r[16];
    __syncthreads();
    #pragma unroll 1
    for (int rep = 0; rep < 2; ++rep) {            // x-dim, pattern A (gmem in)
        const int y = B0 + 16 * q + h + 64 * rep;
        const float* p1 = v1 + base + y * VDIM;
        const float* p2 = v2 + base + y * VDIM;
        #pragma unroll
        for (int j = 0; j < 16; ++j) r[j] = make_float2(p1[t + 8 * j], p2[t + 8 * j]);
        fftA_fwd(r, t, tw, tw4, tw8);
        #pragma unroll
        for (int j = 0; j < 16; ++j) tile[sidxAC(y, t + 8 * j)] = r[j];
    }
    __syncwarp();
    #pragma unroll 1
    for (int rep = 0; rep < 2; ++rep) {            // x-dim, pattern B
        const int y = B0 + q + 16 * h + 64 * rep;
        #pragma unroll
        for (int m = 0; m < 16; ++m) r[m] = tile[sidxAC(y, 16 * t + m)];
        fftB_fwd(r, tw);
        #pragma unroll
        for (int m = 0; m < 16; ++m) tile[sidxAC(y, 16 * t + m)] = r[m];
    }
    __syncthreads();
    #pragma unroll 1
    for (int rep = 0; rep < 2; ++rep) {            // y-dim, pattern A
        const int x = B0 + 16 * q + h + 64 * rep;
        #pragma unroll
        for (int j = 0; j < 16; ++j) r[j] = tile[sidxAC(t + 8 * j, x)];
        fftA_fwd(r, t, tw, tw4, tw8);
        #pragma unroll
        for (int j = 0; j < 16; ++j) tile[sidxAC(t + 8 * j, x)] = r[j];
    }
    __syncthreads();
    #pragma unroll 1
    for (int rep = 0; rep < 2; ++rep) {            // y-dim, pattern B (coalesced out, fp16)
        const int x = xc + 64 * rep;
        #pragma unroll
        for (int m = 0; m < 16; ++m) r[m] = tile[sidxAC(16 * t2 + m, x)];
        fftB_fwd(r, tw);
        #pragma unroll
        for (int m = 0; m < 16; ++m)
            g_Z[base + (size_t)(16 * t2 + m) * VDIM + x] = pack_h2(r[m]);
    }
}

__device__ __forceinline__ float2 Hval(float2 Z, float2 Zn) {
    const float px = Z.x + Zn.x, py = Z.y - Zn.y;   // 2*F1
    const float qx = Z.x - Zn.x, qy = Z.y + Zn.y;   // 2i*F2
    return make_float2(0.25f * (px * qy - py * qx),
                       0.25f * (px * qx + py * qy));
}

// Pass B: forward z-FFT + pointwise H + inverse z-FFT, fused.
// Hermitian: only tileA (rows jy<jy2; self rows fully) is inverted and stored.
// The 1/N^3 output normalization is folded into this store to keep the
// intermediate h values (~1e7 unscaled) inside fp16 range.
__global__ __launch_bounds__(512) void passB() {
    extern __shared__ float2 sm[];
    float2* tile = sm;                              // 64 lines x 128 (z)
    float2* tw = sm + 64 * 128; float2* tw4 = tw + 64; float2* tw8 = tw4 + 16;
    const int xt = blockIdx.x, jy = blockIdx.y, b = blockIdx.z;
    const int jy2 = bneg7(jy);
    const int xt2 = (xt < 2) ? xt : (5 - xt);
    if (jy2 < jy || (jy2 == jy && xt2 < xt)) return;
    const bool full = (jy2 == jy);                  // self rows: store both tiles
    init_tw(tw, tw4, tw8);
    const int tid = threadIdx.x;
    const int t = (tid >> 4) & 7;
    const int l = ((tid >> 7) << 4) | (tid & 15);
    const int xi = l & 31;
    const int gx = (l < 32) ? (32 * xt + xi) : (32 * xt2 + xi);
    const int gy = (l < 32) ? jy : jy2;
    const size_t gb = (size_t)b * VOL + (size_t)gy * VDIM + gx;
    const float SCL = 1.0f / (float)VOL;            // folded normalization
    float2 r[16];
    __syncthreads();
    #pragma unroll
    for (int j = 0; j < 16; ++j) r[j] = unpack_h2(g_Z[gb + (size_t)(t + 8 * j) * SLAB]);
    fftA_fwd(r, t, tw, tw4, tw8);
    #pragma unroll
    for (int j = 0; j < 16; ++j) tile[sidxB(l, t + 8 * j)] = r[j];
    __syncthreads();
    #pragma unroll
    for (int m = 0; m < 16; ++m) r[m] = tile[sidxB(l, 16 * t + m)];
    fftB_fwd(r, tw);
    #pragma unroll
    for (int m = 0; m < 16; ++m) tile[sidxB(l, 16 * t + m)] = r[m];
    __syncthreads();
    // pointwise: warp spans 32 consecutive jz; read-all / sync / write-all
    {
        const int jz = tid & 127, row0 = tid >> 7;
        const int jzn = bneg7(jz);
        #pragma unroll
        for (int k = 0; k < 16; ++k) {
            const int row = row0 + 4 * k;
            const int pr = (row < 32) ? (32 + bneg7(32 * xt + row) - 32 * xt2)
                                      : (bneg7(32 * xt2 + (row - 32)) - 32 * xt);
            r[k] = Hval(tile[sidxB(row, jz)], tile[sidxB(pr, jzn)]);
        }
        __syncthreads();
        #pragma unroll
        for (int k = 0; k < 16; ++k) tile[sidxB(row0 + 4 * k, jz)] = r[k];
    }
    __syncthreads();
    if (full || l < 32) {
        #pragma unroll
        for (int m = 0; m < 16; ++m) r[m] = tile[sidxB(l, 16 * t + m)];
        fftB_inv(r, tw);
        #pragma unroll
        for (int m = 0; m < 16; ++m) tile[sidxB(l, 16 * t + m)] = r[m];
    }
    __syncthreads();
    if (full || l < 32) {
        #pragma unroll
        for (int j = 0; j < 16; ++j) r[j] = tile[sidxB(l, t + 8 * j)];
        fftA_inv(r, t, tw, tw4, tw8);
        #pragma unroll
        for (int j = 0; j < 16; ++j)
            g_Z[gb + (size_t)(t + 8 * j) * SLAB] =
                pack_h2(make_float2(r[j].x * SCL, r[j].y * SCL));
    }
}

// Pass C: gather the stored half-spectrum, mirror-fill conj half in smem,
// inverse FFT along y then x per slab, write real part (already normalized).
__global__ __launch_bounds__(512) void passC(float* __restrict__ out) {
    extern __shared__ float2 sm[];
    float2* tile = sm;
    float2* tw = sm + 128 * 128; float2* tw4 = tw + 64; float2* tw8 = tw4 + 16;
    init_tw(tw, tw4, tw8);
    const int tid = threadIdx.x, w = tid >> 5, lane = tid & 31;
    const int t = lane & 7, q = (lane >> 3) & 1, h = lane >> 4;
    const int B0 = 2 * (w & 7) + 32 * (w >> 3);
    const int t2 = w & 7, xc = 32 * (w >> 3) + lane;
    const size_t base = (size_t)blockIdx.x * SLAB;
    float2 r[16];
    __syncthreads();
    // gather copy-in: load kept rows (jy <= bneg7(jy)); mirror-fill the rest.
    #pragma unroll 1
    for (int jy = w; jy < 128; jy += 16) {
        const int jy2 = bneg7(jy);
        if (jy > jy2) continue;
        #pragma unroll
        for (int k = 0; k < 4; ++k) {
            const int xx = lane + 32 * k;
            const float2 v = unpack_h2(g_Z[base + (size_t)jy * VDIM + xx]);
            tile[sidxAC(jy, xx)] = v;
            if (jy2 != jy) tile[sidxAC(jy2, bneg7(xx))] = make_float2(v.x, -v.y);
        }
    }
    __syncthreads();
    #pragma unroll 1
    for (int rep = 0; rep < 2; ++rep) {            // y-dim, pattern B (from smem)
        const int x = xc + 64 * rep;
        #pragma unroll
        for (int m = 0; m < 16; ++m) r[m] = tile[sidxAC(16 * t2 + m, x)];
        fftB_inv(r, tw);
        #pragma unroll
        for (int m = 0; m < 16; ++m) tile[sidxAC(16 * t2 + m, x)] = r[m];
    }
    __syncthreads();
    #pragma unroll 1
    for (int rep = 0; rep < 2; ++rep) {            // y-dim, pattern A
        const int x = B0 + 16 * q + h + 64 * rep;
        #pragma unroll
        for (int j = 0; j < 16; ++j) r[j] = tile[sidxAC(t + 8 * j, x)];
        fftA_inv(r, t, tw, tw4, tw8);
        #pragma unroll
        for (int j = 0; j < 16; ++j) tile[sidxAC(t + 8 * j, x)] = r[j];
    }
    __syncthreads();
    #pragma unroll 1
    for (int rep = 0; rep < 2; ++rep) {            // x-dim, pattern B
        const int y = B0 + q + 16 * h + 64 * rep;
        #pragma unroll
        for (int m = 0; m < 16; ++m) r[m] = tile[sidxAC(y, 16 * t + m)];
        fftB_inv(r, tw);
        #pragma unroll
        for (int m = 0; m < 16; ++m) tile[sidxAC(y, 16 * t + m)] = r[m];
    }
    __syncwarp();
    #pragma unroll 1
    for (int rep = 0; rep < 2; ++rep) {            // x-dim, pattern A -> out
        const int y = B0 + 16 * q + h + 64 * rep;
        #pragma unroll
        for (int j = 0; j < 16; ++j) r[j] = tile[sidxAC(y, t + 8 * j)];
        fftA_inv(r, t, tw, tw4, tw8);
        #pragma unroll
        for (int j = 0; j < 16; ++j) out[base + y * VDIM + t + 8 * j] = r[j].x;
    }
}

extern "C" void kernel_launch(void* const* d_in, const int* in_sizes, int n_in,
                              void* d_out, int out_size) {
    const float* v1 = (const float*)d_in[0];
    const float* v2 = (const float*)d_in[1];
    float* out = (float*)d_out;
    const int smAC = (128 * 128 + 64 + 16 + 8) * (int)sizeof(float2);  // 131,776 B
    const int smB  = (64 * 128 + 64 + 16 + 8) * (int)sizeof(float2);   //  66,240 B
    cudaFuncSetAttribute(passA, cudaFuncAttributeMaxDynamicSharedMemorySize, smAC);
    cudaFuncSetAttribute(passC, cudaFuncAttributeMaxDynamicSharedMemorySize, smAC);
    cudaFuncSetAttribute(passB, cudaFuncAttributeMaxDynamicSharedMemorySize, smB);
    passA<<<NB * VDIM, 512, smAC>>>(v1, v2);
    passB<<<dim3(4, VDIM, NB), 512, smB>>>();
    passC<<<NB * VDIM, 512, smAC>>>(out);
}